// round 8
// baseline (speedup 1.0000x reference)
#include <cuda_runtime.h>
#include <cuda_bf16.h>
#include <cstdint>

// ============================================================================
// SimpleBNN on GB300 — sm_103 (non-'a': no tcgen05; mma.sync is EMULATED).
// Layers 1/2: XOR-POPC bit-GEMM (exact ternary via sign+mask bitplanes):
//   dot(m,n) = C0[m] - 2 * sum_words popc( (sa ^ sb) & za )
//   Round 8: 3 CTAs/SM (single-buffered 48KB stage, <=85 regs via
//   constant-folded swizzle addressing + halved bv live range).
// Layer 3:    bf16 mma.sync GEMM, w3 = hi+lo split folded into K=8192.
// ============================================================================

#define DINL __device__ __forceinline__

// ---------------- device scratch ----------------
// Bit blocks: (tile*4 + ks) of 128 rows x 128B (32 u32 words = 1024 K-bits),
// 16B chunk c stored at position c ^ ((row>>3)&7)  [bank-conflict-free LDS128]
__device__ __align__(128) uint8_t g_A1s[(size_t)64 * 4 * 16384];  // sign(x) bits
__device__ __align__(128) uint8_t g_A1m[(size_t)64 * 4 * 16384];  // x != 0 bits
__device__ __align__(128) uint8_t g_W1b[(size_t)32 * 4 * 16384];  // sign(w1) bits
__device__ __align__(128) uint8_t g_W2b[(size_t)32 * 4 * 16384];  // sign(w2) bits
__device__ __align__(128) uint8_t g_A2s[(size_t)64 * 4 * 16384];  // sign(a1) bits
__device__ __align__(128) uint8_t g_A2m[(size_t)64 * 4 * 16384];  // a1 != 0 bits
__device__ int g_C0x[8192];                                       // nnz per x row
__device__ int g_C01[8192];                                       // nnz per a1 row
// Layer-3 operands
__device__ __align__(128) uint8_t g_A3[(size_t)64 * 64 * 16384];  // a2 bf16 A-blocks
__device__ __align__(128) uint8_t g_B3[(size_t)4 * 128 * 32768];  // w3 hi|lo bf16 B-blocks

// ---------------- helpers ----------------
DINL uint32_t smem_u32(const void* p) {
    uint32_t a;
    asm("{ .reg .u64 t; cvta.to.shared.u64 t, %1; cvt.u32.u64 %0, t; }" : "=r"(a) : "l"(p));
    return a;
}
DINL uint4 lds128(uint32_t addr) {
    uint4 v;
    asm volatile("ld.shared.v4.u32 {%0,%1,%2,%3}, [%4];"
                 : "=r"(v.x), "=r"(v.y), "=r"(v.z), "=r"(v.w) : "r"(addr));
    return v;
}
DINL uint32_t bf16sgn(float v) {    // sign -> bf16 bits (+-1.0 or 0)
    uint32_t u = __float_as_uint(v);
    return ((u << 1) == 0u) ? 0u : (0x3F80u | ((u >> 31) << 15));
}

#define MBAR_INIT(addr, cnt) \
    asm volatile("mbarrier.init.shared.b64 [%0], %1;" :: "r"(addr), "r"(cnt) : "memory")
#define MBAR_EXPECT_TX(addr, tx) \
    asm volatile("mbarrier.arrive.expect_tx.shared.b64 _, [%0], %1;" \
                 :: "r"(addr), "r"(tx) : "memory")
#define MBAR_WAIT(addr, parity) do {                                          \
    asm volatile("{\n\t.reg .pred P1;\n\t"                                    \
        "WAIT_%=:\n\t"                                                        \
        "mbarrier.try_wait.parity.acquire.cta.shared::cta.b64 P1, [%0], %1, 0x989680;\n\t" \
        "@P1 bra.uni DONE_%=;\n\t"                                            \
        "bra.uni WAIT_%=;\n\t"                                                \
        "DONE_%=:\n\t}"                                                       \
        :: "r"((uint32_t)(addr)), "r"((uint32_t)(parity)) : "memory");        \
} while (0)
#define BULK_G2S(dst, src, bytes, mbar)                                       \
    asm volatile("cp.async.bulk.shared::cluster.global.mbarrier::complete_tx::bytes " \
                 "[%0], [%1], %2, [%3];"                                      \
                 :: "r"((uint32_t)(dst)), "l"(src), "r"((uint32_t)(bytes)),   \
                    "r"((uint32_t)(mbar)) : "memory")

#define LDSM_X4(r, addr)                                                      \
    asm volatile("ldmatrix.sync.aligned.m8n8.x4.shared.b16 {%0,%1,%2,%3}, [%4];" \
        : "=r"((r)[0]), "=r"((r)[1]), "=r"((r)[2]), "=r"((r)[3]) : "r"(addr))
#define LDSM_X2(r, addr)                                                      \
    asm volatile("ldmatrix.sync.aligned.m8n8.x2.shared.b16 {%0,%1}, [%2];"    \
        : "=r"((r)[0]), "=r"((r)[1]) : "r"(addr))

DINL void mma_bf16(float c[4], const uint32_t a[4], uint32_t b0, uint32_t b1) {
    asm volatile(
        "mma.sync.aligned.m16n8k16.row.col.f32.bf16.bf16.f32 "
        "{%0,%1,%2,%3}, {%4,%5,%6,%7}, {%8,%9}, {%0,%1,%2,%3};"
        : "+f"(c[0]), "+f"(c[1]), "+f"(c[2]), "+f"(c[3])
        : "r"(a[0]), "r"(a[1]), "r"(a[2]), "r"(a[3]), "r"(b0), "r"(b1));
}

// ============================================================================
// Prep: pack sign/mask bitplanes, tiled + chunk-swizzled for bulk copy
// ============================================================================
template <int SEL>   // 0: x -> A1s/A1m ; 1: w1 -> W1b ; 2: w2 -> W2b
__global__ void pack_bits(const float* __restrict__ src) {
    uint32_t t = blockIdx.x * 256 + threadIdx.x;     // rows*128 threads
    uint32_t row = t >> 7, w = t & 127;
    const float* p = src + (size_t)row * 4096 + w * 32;
    uint32_t s = 0, m = 0;
    #pragma unroll
    for (int j = 0; j < 32; j += 4) {
        float4 f = *(const float4*)(p + j);
        uint32_t u0 = __float_as_uint(f.x), u1 = __float_as_uint(f.y);
        uint32_t u2 = __float_as_uint(f.z), u3 = __float_as_uint(f.w);
        s |= (u0 >> 31) << j | (u1 >> 31) << (j + 1)
           | (u2 >> 31) << (j + 2) | (u3 >> 31) << (j + 3);
        m |= (uint32_t)((u0 << 1) != 0) << j       | (uint32_t)((u1 << 1) != 0) << (j + 1)
           | (uint32_t)((u2 << 1) != 0) << (j + 2) | (uint32_t)((u3 << 1) != 0) << (j + 3);
    }
    uint32_t rt = row >> 7, r = row & 127, ks = w >> 5, wi = w & 31;
    size_t off = ((size_t)(rt * 4 + ks) * 128 + r) * 128
               + (((wi >> 2) ^ ((r >> 3) & 7)) << 4) + (wi & 3) * 4;
    if (SEL == 0) { *(uint32_t*)(g_A1s + off) = s; *(uint32_t*)(g_A1m + off) = m; }
    else if (SEL == 1) { *(uint32_t*)(g_W1b + off) = s; }
    else               { *(uint32_t*)(g_W2b + off) = s; }
}

// C0[m] = number of nonzero entries in A row m (popc over mask plane)
template <int SEL>   // 0: g_A1m -> g_C0x ; 1: g_A2m -> g_C01
__global__ void c0_kernel() {
    int m = blockIdx.x * 256 + threadIdx.x;          // 8192 threads
    const uint8_t* base = SEL ? g_A2m : g_A1m;
    int rt = m >> 7, r = m & 127, cnt = 0;
    #pragma unroll
    for (int ks = 0; ks < 4; ks++) {
        const uint4* rowp = (const uint4*)(base + ((size_t)(rt * 4 + ks) * 128 + r) * 128);
        #pragma unroll
        for (int c2 = 0; c2 < 8; c2++) {
            uint4 v = rowp[c2];
            cnt += __popc(v.x) + __popc(v.y) + __popc(v.z) + __popc(v.w);
        }
    }
    if (SEL) g_C01[m] = cnt; else g_C0x[m] = cnt;
}

// w3 [1000,4096] f32 -> bf16 hi|lo B-blocks (nt*128+ks): 256 rows x 128B
__global__ void prep_w3k(const float* __restrict__ w3) {
    size_t t = (size_t)blockIdx.x * 256 + threadIdx.x;   // 1,048,576
    int c  = (int)(t & 7);
    int r  = (int)((t >> 3) & 255);
    int ks = (int)((t >> 11) & 127);
    int nt = (int)(t >> 18);
    int n  = nt * 256 + r;
    int kb = ks * 128 + c * 16;
    bool hi = kb < 8192;
    int ke = (hi ? kb : kb - 8192) >> 1;
    float f[8];
    if (n < 1000) {
        const float4* s = (const float4*)(w3 + (size_t)n * 4096 + ke);
        float4 a = s[0], b = s[1];
        f[0] = a.x; f[1] = a.y; f[2] = a.z; f[3] = a.w;
        f[4] = b.x; f[5] = b.y; f[6] = b.z; f[7] = b.w;
    } else {
        #pragma unroll
        for (int i = 0; i < 8; i++) f[i] = 0.0f;
    }
    uint32_t hwd[8];
    #pragma unroll
    for (int i = 0; i < 8; i++) {
        __nv_bfloat16 h = __float2bfloat16(f[i]);
        if (hi) hwd[i] = (uint32_t)__bfloat16_as_ushort(h);
        else    hwd[i] = (uint32_t)__bfloat16_as_ushort(__float2bfloat16(f[i] - __bfloat162float(h)));
    }
    uint4 o;
    o.x = hwd[0] | (hwd[1] << 16); o.y = hwd[2] | (hwd[3] << 16);
    o.z = hwd[4] | (hwd[5] << 16); o.w = hwd[6] | (hwd[7] << 16);
    *(uint4*)(g_B3 + ((size_t)(nt * 128 + ks) * 256 + r) * 128 + (((c ^ (r & 7)) << 4))) = o;
}

// ============================================================================
// bit-GEMM: CTA 128x128, 8 warps (2m x 4n, warp 64x32), lane tile 8m x 8n.
// K = 4096 bits in 4 k-steps of 1024 bits, SINGLE 48KB buffer, 3 CTAs/SM.
// Addressing: swizzle chunk is constant per thread -> addr = (const^kx)+i*128.
// Accumulators packed 2 cells / u32 (16-bit halves, max 4096 < 2^16).
// LAYER 1: out = {sign,mask} bits of (dot + b1) -> g_A2s/g_A2m
// LAYER 2: out = bf16 sign of (dot + b2)        -> g_A3 (layer-3 A layout)
// ============================================================================
static const int BG_STAGE = 49152;
static const int BG_SMEM  = BG_STAGE + 64;          // 49216 -> 3 CTAs/SM

template <int LAYER>
__global__ void __launch_bounds__(256, 3) bitgemm(const float* __restrict__ bias) {
    extern __shared__ __align__(128) uint8_t smem[];
    const int tid = threadIdx.x, lane = tid & 31;
    const int wid = tid >> 5;
    const int g = lane >> 2, c = lane & 3;
    const int mt = blockIdx.x, nt = blockIdx.y;
    const int warp_m = (wid >> 2) * 64, warp_n = (wid & 3) * 32;
    const uint32_t sb = smem_u32(smem);
    const uint32_t mbar = sb + BG_STAGE;

    const uint8_t* As = (LAYER == 1) ? g_A1s : g_A2s;
    const uint8_t* Am = (LAYER == 1) ? g_A1m : g_A2m;
    const uint8_t* Bs = (LAYER == 1) ? g_W1b : g_W2b;
    const int*     C0 = (LAYER == 1) ? g_C0x : g_C01;

    if (tid == 0) MBAR_INIT(mbar, 1);
    __syncthreads();

    auto issue = [&](int ks) {
        MBAR_EXPECT_TX(mbar, BG_STAGE);
        BULK_G2S(sb,         As + (size_t)(mt * 4 + ks) * 16384, 16384, mbar);
        BULK_G2S(sb + 16384, Am + (size_t)(mt * 4 + ks) * 16384, 16384, mbar);
        BULK_G2S(sb + 32768, Bs + (size_t)(nt * 4 + ks) * 16384, 16384, mbar);
    };
    if (tid == 0) issue(0);

    // Constant (per-thread) swizzled base offsets.
    // A rows: warp_m + g*8 + mi  -> swizzle chunk = ((warp_m>>3)+g)&7 == g.
    // B rows: warp_n + c*8 + nj  -> swizzle chunk = ((warp_n>>3)+c)&7 (const).
    const uint32_t cA = (uint32_t)(warp_m + g * 8) * 128 + ((uint32_t)g << 4);
    const uint32_t cB = (uint32_t)(warp_n + c * 8) * 128
                      + (((((uint32_t)warp_n >> 3) + (uint32_t)c) & 7u) << 4);

    uint32_t acc[8][4];   // [mi][p]: cells (2p) low16, (2p+1) high16
    #pragma unroll
    for (int i = 0; i < 8; i++)
        #pragma unroll
        for (int p = 0; p < 4; p++) acc[i][p] = 0u;

    #pragma unroll 1
    for (int ks = 0; ks < 4; ks++) {
        MBAR_WAIT(mbar, ks & 1);
        #pragma unroll
        for (int kc = 0; kc < 8; kc++) {
            const uint32_t kx = (uint32_t)kc << 4;
            const uint32_t aS = sb + (cA ^ kx);           // sign base (+mi*128)
            const uint32_t bB = sb + 32768 + (cB ^ kx);   // B base (+nj*128)
            #pragma unroll
            for (int h = 0; h < 2; h++) {                 // nj halves: 0-3, 4-7
                uint4 bv[4];
                #pragma unroll
                for (int j = 0; j < 4; j++)
                    bv[j] = lds128(bB + (uint32_t)(h * 4 + j) * 128);
                #pragma unroll
                for (int mi = 0; mi < 8; mi++) {
                    uint4 av = lds128(aS + (uint32_t)mi * 128);
                    uint4 mv = lds128(aS + 16384 + (uint32_t)mi * 128);
                    #pragma unroll
                    for (int pp = 0; pp < 2; pp++) {
                        uint32_t pa = __popc((av.x ^ bv[2*pp].x) & mv.x)
                                    + __popc((av.y ^ bv[2*pp].y) & mv.y)
                                    + __popc((av.z ^ bv[2*pp].z) & mv.z)
                                    + __popc((av.w ^ bv[2*pp].w) & mv.w);
                        uint32_t pb = __popc((av.x ^ bv[2*pp+1].x) & mv.x)
                                    + __popc((av.y ^ bv[2*pp+1].y) & mv.y)
                                    + __popc((av.z ^ bv[2*pp+1].z) & mv.z)
                                    + __popc((av.w ^ bv[2*pp+1].w) & mv.w);
                        acc[mi][h * 2 + pp] += pa + (pb << 16);
                    }
                }
            }
        }
        __syncthreads();                    // all warps done with the buffer
        if (ks < 3 && tid == 0) issue(ks + 1);
    }

    // ---------------- epilogue ----------------
    float bn[8];
    #pragma unroll
    for (int nj = 0; nj < 8; nj++) bn[nj] = bias[nt * 128 + warp_n + c * 8 + nj];

    #pragma unroll
    for (int mi = 0; mi < 8; mi++) {
        const int rl = warp_m + g * 8 + mi;
        const int m  = mt * 128 + rl;
        const int c0 = C0[m];
        float v[8];
        #pragma unroll
        for (int p = 0; p < 4; p++) {
            int lo = (int)(acc[mi][p] & 0xFFFFu);
            int hi = (int)(acc[mi][p] >> 16);
            v[2*p]     = (float)(c0 - 2 * lo) + bn[2*p];
            v[2*p + 1] = (float)(c0 - 2 * hi) + bn[2*p + 1];
        }

        if (LAYER == 1) {
            uint32_t bs_ = 0, bm_ = 0;
            #pragma unroll
            for (int nj = 0; nj < 8; nj++) {
                uint32_t u = __float_as_uint(v[nj]);
                bs_ |= (u >> 31) << nj;
                bm_ |= (uint32_t)((u << 1) != 0) << nj;
            }
            uint32_t ws = bs_ << (8 * c), wm = bm_ << (8 * c);
            ws |= __shfl_xor_sync(0xFFFFFFFFu, ws, 1);
            ws |= __shfl_xor_sync(0xFFFFFFFFu, ws, 2);
            wm |= __shfl_xor_sync(0xFFFFFFFFu, wm, 1);
            wm |= __shfl_xor_sync(0xFFFFFFFFu, wm, 2);
            if (c == 0) {
                int nw = nt * 4 + (warp_n >> 5);        // global 32-bit word index
                int ks2 = nw >> 5, wi = nw & 31;
                size_t off = ((size_t)(mt * 4 + ks2) * 128 + rl) * 128
                           + (((wi >> 2) ^ ((rl >> 3) & 7)) << 4) + (wi & 3) * 4;
                *(uint32_t*)(g_A2s + off) = ws;
                *(uint32_t*)(g_A2m + off) = wm;
            }
        } else {
            uint32_t pk[4];
            #pragma unroll
            for (int q = 0; q < 4; q++)
                pk[q] = bf16sgn(v[2 * q]) | (bf16sgn(v[2 * q + 1]) << 16);
            const int n0 = nt * 128 + warp_n + c * 8;
            const int nb = n0 * 2;                       // byte offset in 8192B row
            size_t off = ((size_t)(mt * 64 + (nb >> 7)) * 128 + rl) * 128
                       + ((((uint32_t)(nb >> 4) & 7) ^ ((uint32_t)rl & 7)) << 4);
            *(uint4*)(g_A3 + off) = make_uint4(pk[0], pk[1], pk[2], pk[3]);
        }
    }
}

// ============================================================================
// Layer-3 bf16 GEMM: CTA 128x256, K=8192 (hi|lo), 4-stage bulk pipeline
// ============================================================================
static const int G3_STAGE = 49152;
static const int G3_SMEM  = 4 * G3_STAGE + 64 + 1024;

__global__ void __launch_bounds__(256, 1) gemm3(const float* __restrict__ bias,
                                                float* __restrict__ outf) {
    extern __shared__ __align__(128) uint8_t smem[];
    const int tid = threadIdx.x, lane = tid & 31, wid = tid >> 5;
    const int mt = blockIdx.x, nt = blockIdx.y;
    const int m_w = (wid >> 2) * 64, n_w = (wid & 3) * 64;
    const uint32_t sbase = smem_u32(smem);
    const uint32_t mbar  = sbase + 4 * G3_STAGE;
    float* s_bias = (float*)(smem + 4 * G3_STAGE + 64);

    const uint8_t* Ablk = g_A3 + (size_t)mt * 64 * 16384;
    const uint8_t* Bblk = g_B3 + (size_t)nt * 128 * 32768;

    if (tid == 0) {
        #pragma unroll
        for (int s = 0; s < 4; s++) MBAR_INIT(mbar + 8 * s, 1);
    }
    {
        int n = nt * 256 + tid;
        s_bias[tid] = (n < 1000) ? bias[n] : 0.0f;
    }
    __syncthreads();

    auto issue = [&](int ks) {
        if (tid == 0) {
            const int sl = ks & 3;
            const uint32_t mb = mbar + 8 * sl;
            MBAR_EXPECT_TX(mb, G3_STAGE);
            BULK_G2S(sbase + sl * G3_STAGE,         Ablk + (size_t)(ks & 63) * 16384, 16384, mb);
            BULK_G2S(sbase + sl * G3_STAGE + 16384, Bblk + (size_t)ks * 32768,        32768, mb);
        }
    };

    float cf[4][8][4];
    #pragma unroll
    for (int a = 0; a < 4; a++)
        #pragma unroll
        for (int b = 0; b < 8; b++)
            #pragma unroll
            for (int q = 0; q < 4; q++) cf[a][b][q] = 0.0f;

    #pragma unroll
    for (int s = 0; s < 4; s++) issue(s);

    const uint32_t a_row = (uint32_t)(m_w + ((lane >> 3) & 1) * 8 + (lane & 7));
    const uint32_t a_chi = (uint32_t)(lane >> 4);
    const uint32_t b_row = (uint32_t)(n_w + (lane & 7));
    const uint32_t b_chi = (uint32_t)((lane >> 3) & 1);

    #pragma unroll 1
    for (int ks = 0; ks < 128; ks++) {
        const int sl = ks & 3;
        MBAR_WAIT(mbar + 8 * sl, (ks >> 2) & 1);
        const uint32_t sA = sbase + sl * G3_STAGE;
        const uint32_t sB = sA + 16384;

        #pragma unroll
        for (int kst = 0; kst < 4; kst++) {
            uint32_t a[4][4];
            #pragma unroll
            for (int mi = 0; mi < 4; mi++) {
                uint32_t rl = a_row + mi * 16;
                uint32_t cc = (uint32_t)(kst * 2) + a_chi;
                LDSM_X4(a[mi], sA + rl * 128 + (((cc ^ (rl & 7)) << 4)));
            }
            uint32_t b[8][2];
            #pragma unroll
            for (int ni = 0; ni < 8; ni++) {
                uint32_t rl = b_row + ni * 8;
                uint32_t cc = (uint32_t)(kst * 2) + b_chi;
                LDSM_X2(b[ni], sB + rl * 128 + (((cc ^ (rl & 7)) << 4)));
            }
            #pragma unroll
            for (int mi = 0; mi < 4; mi++)
                #pragma unroll
                for (int ni = 0; ni < 8; ni++)
                    mma_bf16(cf[mi][ni], a[mi], b[ni][0], b[ni][1]);
        }
        __syncthreads();
        if (ks + 4 < 128) issue(ks + 4);
    }

    const int g = lane >> 2, t4 = lane & 3;
    #pragma unroll
    for (int mi = 0; mi < 4; mi++) {
        const int rl0 = m_w + mi * 16 + g;
        #pragma unroll
        for (int ni = 0; ni < 8; ni++) {
            const int nl = n_w + ni * 8 + t4 * 2;
            const int ng = nt * 256 + nl;
            const size_t r0 = (size_t)(mt * 128 + rl0);
            float f0 = cf[mi][ni][0] + s_bias[nl];
            float f1 = cf[mi][ni][1] + s_bias[nl + 1];
            float f2 = cf[mi][ni][2] + s_bias[nl];
            float f3 = cf[mi][ni][3] + s_bias[nl + 1];
            if (ng < 1000) {
                outf[r0 * 1000 + ng]       = f0;
                outf[(r0 + 8) * 1000 + ng] = f2;
            }
            if (ng + 1 < 1000) {
                outf[r0 * 1000 + ng + 1]       = f1;
                outf[(r0 + 8) * 1000 + ng + 1] = f3;
            }
        }
    }
}

// ============================================================================
// kernel_launch — launch index 3 (the profiled one) = bitgemm<1>
// ============================================================================
extern "C" void kernel_launch(void* const* d_in, const int* in_sizes, int n_in,
                              void* d_out, int out_size) {
    (void)in_sizes; (void)n_in; (void)out_size;
    const float* x  = (const float*)d_in[0];
    const float* w1 = (const float*)d_in[1];
    const float* b1 = (const float*)d_in[2];
    const float* w2 = (const float*)d_in[3];
    const float* b2 = (const float*)d_in[4];
    const float* w3 = (const float*)d_in[5];
    const float* b3 = (const float*)d_in[6];
    float* out = (float*)d_out;

    cudaFuncSetAttribute(bitgemm<1>, cudaFuncAttributeMaxDynamicSharedMemorySize, BG_SMEM);
    cudaFuncSetAttribute(bitgemm<2>, cudaFuncAttributeMaxDynamicSharedMemorySize, BG_SMEM);
    cudaFuncSetAttribute(gemm3,      cudaFuncAttributeMaxDynamicSharedMemorySize, G3_SMEM);

    pack_bits<0><<<4096, 256>>>(x);                       // 0
    pack_bits<1><<<2048, 256>>>(w1);                      // 1
    c0_kernel<0><<<32, 256>>>();                          // 2
    bitgemm<1><<<dim3(64, 32), 256, BG_SMEM>>>(b1);       // 3  <- profiled
    pack_bits<2><<<2048, 256>>>(w2);                      // 4
    c0_kernel<1><<<32, 256>>>();                          // 5
    bitgemm<2><<<dim3(64, 32), 256, BG_SMEM>>>(b2);       // 6
    prep_w3k<<<4096, 256>>>(w3);                          // 7
    gemm3<<<dim3(64, 4), 256, G3_SMEM>>>(b3, out);        // 8
}

// round 9
// speedup vs baseline: 1.5835x; 1.5835x over previous
#include <cuda_runtime.h>
#include <cuda_bf16.h>
#include <cstdint>

// ============================================================================
// SimpleBNN on GB300 — sm_103.
// KEY MEASURED FACT: bf16 mma.sync = real tensor HW (~213 TMAC/s); s8 mma is
// emulated (slow); POPC is ~1/8-rate. => ALL THREE layers run as bf16 HMMA
// GEMMs. Ternary operands are exact in bf16; f32 accum of +-1 terms is exact.
//   L1: sign(x) @ sign(w1)^T + b1 -> sign -> bf16 A-tiles
//   L2: a1 @ sign(w2)^T + b2      -> sign -> bf16 A-tiles
//   L3: a2 @ w3^T + b3 (w3 = hi+lo bf16 split folded into K=8192)
// Mainloop (all layers): 2x cp.async.bulk/stage, 4-stage mbarrier pipeline,
// CTA 128x256, 8 warps, ldmatrix + mma.sync.m16n8k16.bf16.
// ============================================================================

#define DINL __device__ __forceinline__

// ---------------- device scratch ----------------
// A-tiles: blocks (mt*64 + ks) of 128 rows x 128B (64 bf16 k-elems), chunk c
//          at position c ^ (row&7). B-tiles: blocks of 256 rows x 128B.
__device__ __align__(128) uint8_t g_Ax [(size_t)64 * 64 * 16384];  // sign(x)   64MB
__device__ __align__(128) uint8_t g_W1t[(size_t)16 * 64 * 32768];  // sign(w1)  32MB
__device__ __align__(128) uint8_t g_W2t[(size_t)16 * 64 * 32768];  // sign(w2)  32MB
__device__ __align__(128) uint8_t g_T1 [(size_t)64 * 64 * 16384];  // a1        64MB
__device__ __align__(128) uint8_t g_T2 [(size_t)64 * 64 * 16384];  // a2        64MB
__device__ __align__(128) uint8_t g_B3 [(size_t)4 * 128 * 32768];  // w3 hi|lo  16MB

// ---------------- helpers ----------------
DINL uint32_t smem_u32(const void* p) {
    uint32_t a;
    asm("{ .reg .u64 t; cvta.to.shared.u64 t, %1; cvt.u32.u64 %0, t; }" : "=r"(a) : "l"(p));
    return a;
}
DINL uint32_t bf16sgn(float v) {    // sign -> bf16 bits (+-1.0 or 0)
    uint32_t u = __float_as_uint(v);
    return ((u << 1) == 0u) ? 0u : (0x3F80u | ((u >> 31) << 15));
}

#define MBAR_INIT(addr, cnt) \
    asm volatile("mbarrier.init.shared.b64 [%0], %1;" :: "r"(addr), "r"(cnt) : "memory")
#define MBAR_EXPECT_TX(addr, tx) \
    asm volatile("mbarrier.arrive.expect_tx.shared.b64 _, [%0], %1;" \
                 :: "r"(addr), "r"(tx) : "memory")
#define MBAR_WAIT(addr, parity) do {                                          \
    asm volatile("{\n\t.reg .pred P1;\n\t"                                    \
        "WAIT_%=:\n\t"                                                        \
        "mbarrier.try_wait.parity.acquire.cta.shared::cta.b64 P1, [%0], %1, 0x989680;\n\t" \
        "@P1 bra.uni DONE_%=;\n\t"                                            \
        "bra.uni WAIT_%=;\n\t"                                                \
        "DONE_%=:\n\t}"                                                       \
        :: "r"((uint32_t)(addr)), "r"((uint32_t)(parity)) : "memory");        \
} while (0)
#define BULK_G2S(dst, src, bytes, mbar)                                       \
    asm volatile("cp.async.bulk.shared::cluster.global.mbarrier::complete_tx::bytes " \
                 "[%0], [%1], %2, [%3];"                                      \
                 :: "r"((uint32_t)(dst)), "l"(src), "r"((uint32_t)(bytes)),   \
                    "r"((uint32_t)(mbar)) : "memory")

#define LDSM_X4(r, addr)                                                      \
    asm volatile("ldmatrix.sync.aligned.m8n8.x4.shared.b16 {%0,%1,%2,%3}, [%4];" \
        : "=r"((r)[0]), "=r"((r)[1]), "=r"((r)[2]), "=r"((r)[3]) : "r"(addr))
#define LDSM_X2(r, addr)                                                      \
    asm volatile("ldmatrix.sync.aligned.m8n8.x2.shared.b16 {%0,%1}, [%2];"    \
        : "=r"((r)[0]), "=r"((r)[1]) : "r"(addr))

DINL void mma_bf16(float c[4], const uint32_t a[4], uint32_t b0, uint32_t b1) {
    asm volatile(
        "mma.sync.aligned.m16n8k16.row.col.f32.bf16.bf16.f32 "
        "{%0,%1,%2,%3}, {%4,%5,%6,%7}, {%8,%9}, {%0,%1,%2,%3};"
        : "+f"(c[0]), "+f"(c[1]), "+f"(c[2]), "+f"(c[3])
        : "r"(a[0]), "r"(a[1]), "r"(a[2]), "r"(a[3]), "r"(b0), "r"(b1));
}

// ============================================================================
// Prep kernels: binarize to bf16, tile + chunk-swizzle for bulk copy
// ============================================================================

// x [8192,4096] f32 -> g_Ax bf16 sign A-tiles
__global__ void prep_actbf16(const float* __restrict__ x) {
    uint32_t t = blockIdx.x * 256 + threadIdx.x;     // 4,194,304
    uint32_t c  = t & 7;
    uint32_t r  = (t >> 3) & 127;
    uint32_t ks = (t >> 10) & 63;
    uint32_t mt = t >> 16;
    const float4* s = (const float4*)(x + ((size_t)(mt * 128 + r) * 4096 + ks * 64 + c * 8));
    float4 f0 = s[0], f1 = s[1];
    uint4 o;
    o.x = bf16sgn(f0.x) | (bf16sgn(f0.y) << 16);
    o.y = bf16sgn(f0.z) | (bf16sgn(f0.w) << 16);
    o.z = bf16sgn(f1.x) | (bf16sgn(f1.y) << 16);
    o.w = bf16sgn(f1.z) | (bf16sgn(f1.w) << 16);
    *(uint4*)(g_Ax + ((size_t)(mt * 64 + ks) * 128 + r) * 128 + ((c ^ (r & 7)) << 4)) = o;
}

// w [4096,4096] f32 -> bf16 sign B-tiles (256 rows x 128B blocks)
template <int SEL>
__global__ void prep_wbf16(const float* __restrict__ w) {
    uint32_t t = blockIdx.x * 256 + threadIdx.x;     // 2,097,152
    uint32_t c  = t & 7;
    uint32_t r  = (t >> 3) & 255;
    uint32_t ks = (t >> 11) & 63;
    uint32_t nt = t >> 17;
    const float4* s = (const float4*)(w + ((size_t)(nt * 256 + r) * 4096 + ks * 64 + c * 8));
    float4 f0 = s[0], f1 = s[1];
    uint4 o;
    o.x = bf16sgn(f0.x) | (bf16sgn(f0.y) << 16);
    o.y = bf16sgn(f0.z) | (bf16sgn(f0.w) << 16);
    o.z = bf16sgn(f1.x) | (bf16sgn(f1.y) << 16);
    o.w = bf16sgn(f1.z) | (bf16sgn(f1.w) << 16);
    uint8_t* base = (SEL == 0) ? g_W1t : g_W2t;
    *(uint4*)(base + ((size_t)(nt * 64 + ks) * 256 + r) * 128 + ((c ^ (r & 7)) << 4)) = o;
}

// w3 [1000,4096] f32 -> bf16 hi|lo B-blocks (nt*128+ks): 256 rows x 128B
__global__ void prep_w3k(const float* __restrict__ w3) {
    size_t t = (size_t)blockIdx.x * 256 + threadIdx.x;   // 1,048,576
    int c  = (int)(t & 7);
    int r  = (int)((t >> 3) & 255);
    int ks = (int)((t >> 11) & 127);
    int nt = (int)(t >> 18);
    int n  = nt * 256 + r;
    int kb = ks * 128 + c * 16;
    bool hi = kb < 8192;
    int ke = (hi ? kb : kb - 8192) >> 1;
    float f[8];
    if (n < 1000) {
        const float4* s = (const float4*)(w3 + (size_t)n * 4096 + ke);
        float4 a = s[0], b = s[1];
        f[0] = a.x; f[1] = a.y; f[2] = a.z; f[3] = a.w;
        f[4] = b.x; f[5] = b.y; f[6] = b.z; f[7] = b.w;
    } else {
        #pragma unroll
        for (int i = 0; i < 8; i++) f[i] = 0.0f;
    }
    uint32_t hwd[8];
    #pragma unroll
    for (int i = 0; i < 8; i++) {
        __nv_bfloat16 h = __float2bfloat16(f[i]);
        if (hi) hwd[i] = (uint32_t)__bfloat16_as_ushort(h);
        else    hwd[i] = (uint32_t)__bfloat16_as_ushort(__float2bfloat16(f[i] - __bfloat162float(h)));
    }
    uint4 o;
    o.x = hwd[0] | (hwd[1] << 16); o.y = hwd[2] | (hwd[3] << 16);
    o.z = hwd[4] | (hwd[5] << 16); o.w = hwd[6] | (hwd[7] << 16);
    *(uint4*)(g_B3 + ((size_t)(nt * 128 + ks) * 256 + r) * 128 + (((c ^ (r & 7)) << 4))) = o;
}

// ============================================================================
// Unified bf16 GEMM: CTA 128x256, 8 warps (2m x 4n), warp tile 64x64,
// stage = A 16KB + B 32KB (64 k-elems), 4-stage cp.async.bulk pipeline.
// LAYER 1: A=g_Ax,  B=g_W1t, K=4096, epi: sign(acc+b) -> g_T1 (A-tiles)
// LAYER 2: A=g_T1,  B=g_W2t, K=4096, epi: sign(acc+b) -> g_T2 (A-tiles)
// LAYER 3: A=g_T2 (ks&63 fold), B=g_B3, K=8192, epi: acc+b -> float out
// ============================================================================
static const int G_STAGE = 49152;
static const int G_SMEM  = 4 * G_STAGE + 64 + 1024;

template <int LAYER>
__global__ void __launch_bounds__(256, 1) gemm_bf16(const float* __restrict__ bias,
                                                    float* __restrict__ outf) {
    constexpr int KSTG = (LAYER == 3) ? 128 : 64;

    extern __shared__ __align__(128) uint8_t smem[];
    const int tid = threadIdx.x, lane = tid & 31, wid = tid >> 5;
    const int mt = blockIdx.x, nt = blockIdx.y;
    const int m_w = (wid >> 2) * 64, n_w = (wid & 3) * 64;
    const uint32_t sbase = smem_u32(smem);
    const uint32_t mbar  = sbase + 4 * G_STAGE;
    float* s_bias = (float*)(smem + 4 * G_STAGE + 64);

    const uint8_t* Ablk = (LAYER == 1) ? g_Ax + (size_t)mt * 64 * 16384
                        : (LAYER == 2) ? g_T1 + (size_t)mt * 64 * 16384
                                       : g_T2 + (size_t)mt * 64 * 16384;
    const uint8_t* Bblk = (LAYER == 1) ? g_W1t + (size_t)nt * 64 * 32768
                        : (LAYER == 2) ? g_W2t + (size_t)nt * 64 * 32768
                                       : g_B3  + (size_t)nt * 128 * 32768;

    if (tid == 0) {
        #pragma unroll
        for (int s = 0; s < 4; s++) MBAR_INIT(mbar + 8 * s, 1);
    }
    {
        int n = nt * 256 + tid;
        s_bias[tid] = (LAYER == 3) ? ((n < 1000) ? bias[n] : 0.0f) : bias[n];
    }
    __syncthreads();

    auto issue = [&](int ks) {
        if (tid == 0) {
            const int sl = ks & 3;
            const uint32_t mb = mbar + 8 * sl;
            MBAR_EXPECT_TX(mb, G_STAGE);
            const size_t ak = (LAYER == 3) ? (size_t)(ks & 63) : (size_t)ks;
            BULK_G2S(sbase + sl * G_STAGE,         Ablk + ak * 16384,          16384, mb);
            BULK_G2S(sbase + sl * G_STAGE + 16384, Bblk + (size_t)ks * 32768,  32768, mb);
        }
    };

    float cf[4][8][4];
    #pragma unroll
    for (int a = 0; a < 4; a++)
        #pragma unroll
        for (int b = 0; b < 8; b++)
            #pragma unroll
            for (int q = 0; q < 4; q++) cf[a][b][q] = 0.0f;

    #pragma unroll
    for (int s = 0; s < 4; s++) issue(s);

    const uint32_t a_row = (uint32_t)(m_w + ((lane >> 3) & 1) * 8 + (lane & 7));
    const uint32_t a_chi = (uint32_t)(lane >> 4);
    const uint32_t b_row = (uint32_t)(n_w + (lane & 7));
    const uint32_t b_chi = (uint32_t)((lane >> 3) & 1);

    #pragma unroll 1
    for (int ks = 0; ks < KSTG; ks++) {
        const int sl = ks & 3;
        MBAR_WAIT(mbar + 8 * sl, (ks >> 2) & 1);
        const uint32_t sA = sbase + sl * G_STAGE;
        const uint32_t sB = sA + 16384;

        #pragma unroll
        for (int kst = 0; kst < 4; kst++) {
            uint32_t a[4][4];
            #pragma unroll
            for (int mi = 0; mi < 4; mi++) {
                uint32_t rl = a_row + mi * 16;
                uint32_t cc = (uint32_t)(kst * 2) + a_chi;
                LDSM_X4(a[mi], sA + rl * 128 + (((cc ^ (rl & 7)) << 4)));
            }
            uint32_t b[8][2];
            #pragma unroll
            for (int ni = 0; ni < 8; ni++) {
                uint32_t rl = b_row + ni * 8;
                uint32_t cc = (uint32_t)(kst * 2) + b_chi;
                LDSM_X2(b[ni], sB + rl * 128 + (((cc ^ (rl & 7)) << 4)));
            }
            #pragma unroll
            for (int mi = 0; mi < 4; mi++)
                #pragma unroll
                for (int ni = 0; ni < 8; ni++)
                    mma_bf16(cf[mi][ni], a[mi], b[ni][0], b[ni][1]);
        }
        __syncthreads();
        if (ks + 4 < KSTG) issue(ks + 4);
    }

    // ---------------- epilogue ----------------
    const int g = lane >> 2, t4 = lane & 3;
    #pragma unroll
    for (int mi = 0; mi < 4; mi++) {
        const int rl0 = m_w + mi * 16 + g;               // rows rl0, rl0+8
        #pragma unroll
        for (int ni = 0; ni < 8; ni++) {
            const int nl = n_w + ni * 8 + t4 * 2;        // cols nl, nl+1
            const int ng = nt * 256 + nl;
            const float b0 = s_bias[nl], b1 = s_bias[nl + 1];
            float f0 = cf[mi][ni][0] + b0;
            float f1 = cf[mi][ni][1] + b1;
            float f2 = cf[mi][ni][2] + b0;
            float f3 = cf[mi][ni][3] + b1;
            if constexpr (LAYER == 3) {
                const size_t r0 = (size_t)(mt * 128 + rl0);
                if (ng < 1000) {
                    outf[r0 * 1000 + ng]       = f0;
                    outf[(r0 + 8) * 1000 + ng] = f2;
                }
                if (ng + 1 < 1000) {
                    outf[r0 * 1000 + ng + 1]       = f1;
                    outf[(r0 + 8) * 1000 + ng + 1] = f3;
                }
            } else {
                uint8_t* T = (LAYER == 1) ? g_T1 : g_T2;
                uint32_t p0 = bf16sgn(f0) | (bf16sgn(f1) << 16);
                uint32_t p1 = bf16sgn(f2) | (bf16sgn(f3) << 16);
                const uint32_t nb = (uint32_t)ng * 2;     // byte offset in 8192B row
                const uint32_t ks2 = nb >> 7;
                const uint32_t chk = (nb >> 4) & 7, sub = nb & 15;
                uint8_t* blk = T + (size_t)(mt * 64 + ks2) * 16384;
                uint32_t o0 = (uint32_t)rl0 * 128 + ((chk ^ ((uint32_t)rl0 & 7)) << 4) + sub;
                uint32_t o1 = (uint32_t)(rl0 + 8) * 128 + ((chk ^ ((uint32_t)(rl0 + 8) & 7)) << 4) + sub;
                *(uint32_t*)(blk + o0) = p0;
                *(uint32_t*)(blk + o1) = p1;
            }
        }
    }
}

// ============================================================================
// kernel_launch — launch index 3 (the profiled one) = gemm_bf16<1>
// ============================================================================
extern "C" void kernel_launch(void* const* d_in, const int* in_sizes, int n_in,
                              void* d_out, int out_size) {
    (void)in_sizes; (void)n_in; (void)out_size;
    const float* x  = (const float*)d_in[0];
    const float* w1 = (const float*)d_in[1];
    const float* b1 = (const float*)d_in[2];
    const float* w2 = (const float*)d_in[3];
    const float* b2 = (const float*)d_in[4];
    const float* w3 = (const float*)d_in[5];
    const float* b3 = (const float*)d_in[6];
    float* out = (float*)d_out;

    cudaFuncSetAttribute(gemm_bf16<1>, cudaFuncAttributeMaxDynamicSharedMemorySize, G_SMEM);
    cudaFuncSetAttribute(gemm_bf16<2>, cudaFuncAttributeMaxDynamicSharedMemorySize, G_SMEM);
    cudaFuncSetAttribute(gemm_bf16<3>, cudaFuncAttributeMaxDynamicSharedMemorySize, G_SMEM);

    prep_actbf16<<<16384, 256>>>(x);                         // 0
    prep_wbf16<0><<<8192, 256>>>(w1);                        // 1
    prep_w3k<<<4096, 256>>>(w3);                             // 2
    gemm_bf16<1><<<dim3(64, 16), 256, G_SMEM>>>(b1, nullptr);// 3  <- profiled
    prep_wbf16<1><<<8192, 256>>>(w2);                        // 4
    gemm_bf16<2><<<dim3(64, 16), 256, G_SMEM>>>(b2, nullptr);// 5
    gemm_bf16<3><<<dim3(64, 4),  256, G_SMEM>>>(b3, out);    // 6
}